// round 11
// baseline (speedup 1.0000x reference)
#include <cuda_runtime.h>
#include <math.h>

#define NUM_CLASSES 10000
#define FEATURE_DIM 512

#define GRID_BLOCKS 148          // <= SM count (B300:148, GB300:152) -> one wave,
                                 // all CTAs co-resident, grid spin-sync is safe
#define BLOCK_THREADS 512        // 16 warps
#define TOTAL_WARPS   (GRID_BLOCKS * (BLOCK_THREADS / 32))   // 2368

// Scratch (__device__ globals). Zero at module load (.bss); the kernel restores
// everything to zero each execution, so graph replays are deterministic.
__device__ float        g_dsum[NUM_CLASSES];
__device__ int          g_count[NUM_CLASSES];
__device__ float        g_loss;
__device__ unsigned int g_ticket;

// ---------------------------------------------------------------------------
// Single persistent kernel, one wave.
// Phase 1: warp-strided samples; dist = ||feat_i - centers[label_i]||;
//          spread-address REDG into dsum[lbl], count[lbl].
// Grid sync: fence + ticket (148 arrivals) + spin.
// Phase 2: one class per thread across the whole grid; partial = dsum/count;
//          block-reduce; REDG into g_loss; second ticket; last block writes
//          the scalar and re-zeroes g_loss/g_ticket.
// ---------------------------------------------------------------------------
__global__ void __launch_bounds__(BLOCK_THREADS) centerloss_kernel(
    const float* __restrict__ feat,
    const int*   __restrict__ label,
    const float* __restrict__ centers,
    float*       __restrict__ out,
    int batch, float inv_batch)
{
    const int tid         = threadIdx.x;
    const int lane        = tid & 31;
    const int warp_local  = tid >> 5;
    const int warp_global = blockIdx.x * (BLOCK_THREADS / 32) + warp_local;

    // ---------------- Phase 1: distances ----------------
    for (int w = warp_global; w < batch; w += TOTAL_WARPS) {
        const int lbl = label[w];                          // warp-broadcast load

        const float4* __restrict__ f =
            reinterpret_cast<const float4*>(feat + (size_t)w * FEATURE_DIM);
        const float4* __restrict__ c =
            reinterpret_cast<const float4*>(centers + (size_t)lbl * FEATURE_DIM);

        float acc = 0.0f;
        #pragma unroll
        for (int j = 0; j < FEATURE_DIM / 4 / 32; j++) {   // 4 iters -> 8 LDG.128 batched
            float4 a = f[lane + j * 32];                   // feat: streamed once
            float4 b = __ldg(&c[lane + j * 32]);           // centers: L2 reuse
            float dx = a.x - b.x;
            float dy = a.y - b.y;
            float dz = a.z - b.z;
            float dw = a.w - b.w;
            acc = fmaf(dx, dx, acc);
            acc = fmaf(dy, dy, acc);
            acc = fmaf(dz, dz, acc);
            acc = fmaf(dw, dw, acc);
        }

        #pragma unroll
        for (int o = 16; o > 0; o >>= 1)
            acc += __shfl_xor_sync(0xffffffffu, acc, o);

        if (lane == 0) {
            atomicAdd(&g_dsum[lbl], sqrtf(acc));           // spread-address REDG
            atomicAdd(&g_count[lbl], 1);
        }
    }

    // ---------------- Grid sync (148 arrivals) ----------------
    __syncthreads();
    if (tid == 0) {
        __threadfence();                                   // my atomics before my arrive
        atomicAdd(&g_ticket, 1u);
        volatile unsigned int* tp = &g_ticket;
        while (*tp < (unsigned)gridDim.x) {                // all CTAs resident: no deadlock
            __nanosleep(64);
        }
    }
    __syncthreads();
    __threadfence();                                       // acquire side of the sync

    // ---------------- Phase 2: class reduction, whole grid ----------------
    float partial = 0.0f;
    const int cls = blockIdx.x * BLOCK_THREADS + tid;      // 75776 threads >= 10000
    if (cls < NUM_CLASSES) {
        int   cnt = __ldcg(&g_count[cls]);
        float ds  = __ldcg(&g_dsum[cls]);
        g_count[cls] = 0;                                  // restore invariant
        g_dsum[cls]  = 0.0f;
        if (cnt > 0) partial = ds / (float)cnt;
    }

    #pragma unroll
    for (int o = 16; o > 0; o >>= 1)
        partial += __shfl_xor_sync(0xffffffffu, partial, o);

    __shared__ float s[BLOCK_THREADS / 32];
    if (lane == 0) s[warp_local] = partial;
    __syncthreads();

    if (tid == 0) {
        float bsum = 0.0f;
        #pragma unroll
        for (int k = 0; k < BLOCK_THREADS / 32; k++) bsum += s[k];
        atomicAdd(&g_loss, bsum);                          // 148 same-address REDG: cheap
        __threadfence();                                   // order g_loss add before ticket
        unsigned t = atomicAdd(&g_ticket, 1u);             // counts grid .. 2*grid-1
        if (t == 2u * gridDim.x - 1u) {
            // every block's g_loss add is fenced before its ticket increment
            out[0]   = __ldcg(&g_loss) * inv_batch;
            g_loss   = 0.0f;                               // restore invariants
            g_ticket = 0u;                                 // safe: all spins already exited
        }
    }
}

// ---------------------------------------------------------------------------
// launch: ONE kernel node.
// ---------------------------------------------------------------------------
extern "C" void kernel_launch(void* const* d_in, const int* in_sizes, int n_in,
                              void* d_out, int out_size)
{
    const float* feat    = (const float*)d_in[0];
    const int*   label   = (const int*)d_in[1];
    const float* centers = (const float*)d_in[2];
    float*       out     = (float*)d_out;

    const int batch = in_sizes[1];                         // 16384

    centerloss_kernel<<<GRID_BLOCKS, BLOCK_THREADS>>>(
        feat, label, centers, out, batch, 1.0f / (float)batch);
}

// round 12
// speedup vs baseline: 1.0381x; 1.0381x over previous
#include <cuda_runtime.h>
#include <math.h>

#define NUM_CLASSES 10000
#define FEATURE_DIM 512

#define BLOCK_THREADS 1024       // 32 warps/CTA
#define GRID_BLOCKS   296        // 2 CTAs/SM * 148 SMs; <= 152*2 on GB300 too,
                                 // so ALL CTAs are co-resident (one wave) and
                                 // the grid spin-sync cannot deadlock.
#define TOTAL_WARPS   (GRID_BLOCKS * (BLOCK_THREADS / 32))   // 9472

// Scratch (__device__ globals). Zero at module load (.bss); the kernel restores
// everything to zero each execution, so graph replays are deterministic.
__device__ float        g_dsum[NUM_CLASSES];
__device__ int          g_count[NUM_CLASSES];
__device__ float        g_loss;
__device__ unsigned int g_ticket;

// ---------------------------------------------------------------------------
// Single persistent kernel, exactly one wave, 100% occupancy.
// Phase 1: warp-strided samples; dist = ||feat_i - centers[label_i]||;
//          spread-address REDG into dsum[lbl], count[lbl].
// Grid sync: fence + ticket (296 arrivals) + spin.
// Phase 2: one class per thread across the grid; partial = dsum/count;
//          block-reduce; REDG into g_loss; second ticket; last arrival writes
//          the scalar and restores all invariants.
// ---------------------------------------------------------------------------
__global__ void __launch_bounds__(BLOCK_THREADS, 2) centerloss_kernel(
    const float* __restrict__ feat,
    const int*   __restrict__ label,
    const float* __restrict__ centers,
    float*       __restrict__ out,
    int batch, float inv_batch)
{
    const int tid         = threadIdx.x;
    const int lane        = tid & 31;
    const int warp_local  = tid >> 5;
    const int warp_global = blockIdx.x * (BLOCK_THREADS / 32) + warp_local;

    // ---------------- Phase 1: distances (memory-bound core) ----------------
    for (int w = warp_global; w < batch; w += TOTAL_WARPS) {   // ~2 samples/warp
        const int lbl = label[w];                          // warp-broadcast load

        const float4* __restrict__ f =
            reinterpret_cast<const float4*>(feat + (size_t)w * FEATURE_DIM);
        const float4* __restrict__ c =
            reinterpret_cast<const float4*>(centers + (size_t)lbl * FEATURE_DIM);

        float acc = 0.0f;
        #pragma unroll
        for (int j = 0; j < FEATURE_DIM / 4 / 32; j++) {   // 4 iters -> 8 LDG.128 batched
            float4 a = f[lane + j * 32];                   // feat: streamed once
            float4 b = __ldg(&c[lane + j * 32]);           // centers: L2 reuse
            float dx = a.x - b.x;
            float dy = a.y - b.y;
            float dz = a.z - b.z;
            float dw = a.w - b.w;
            acc = fmaf(dx, dx, acc);
            acc = fmaf(dy, dy, acc);
            acc = fmaf(dz, dz, acc);
            acc = fmaf(dw, dw, acc);
        }

        #pragma unroll
        for (int o = 16; o > 0; o >>= 1)
            acc += __shfl_xor_sync(0xffffffffu, acc, o);

        if (lane == 0) {
            atomicAdd(&g_dsum[lbl], sqrtf(acc));           // spread-address REDG
            atomicAdd(&g_count[lbl], 1);
        }
    }

    // ---------------- Grid sync (296 arrivals, one wave) ----------------
    __syncthreads();
    if (tid == 0) {
        __threadfence();                                   // my atomics before my arrive
        atomicAdd(&g_ticket, 1u);
        volatile unsigned int* tp = &g_ticket;
        while (*tp < (unsigned)gridDim.x) {                // all CTAs resident
            __nanosleep(64);
        }
    }
    __syncthreads();
    __threadfence();                                       // acquire side

    // ---------------- Phase 2: class reduction, whole grid ----------------
    float partial = 0.0f;
    const int cls = blockIdx.x * BLOCK_THREADS + tid;      // 303104 threads >= 10000
    if (cls < NUM_CLASSES) {
        int   cnt = __ldcg(&g_count[cls]);
        float ds  = __ldcg(&g_dsum[cls]);
        g_count[cls] = 0;                                  // restore invariant
        g_dsum[cls]  = 0.0f;
        if (cnt > 0) partial = ds / (float)cnt;
    }

    #pragma unroll
    for (int o = 16; o > 0; o >>= 1)
        partial += __shfl_xor_sync(0xffffffffu, partial, o);

    __shared__ float s[BLOCK_THREADS / 32];
    if (lane == 0) s[warp_local] = partial;
    __syncthreads();

    if (tid == 0) {
        float bsum = 0.0f;
        #pragma unroll
        for (int k = 0; k < BLOCK_THREADS / 32; k++) bsum += s[k];
        atomicAdd(&g_loss, bsum);                          // 296 same-address REDG
        __threadfence();                                   // g_loss add before ticket
        unsigned t = atomicAdd(&g_ticket, 1u);             // counts grid .. 2*grid-1
        if (t == 2u * gridDim.x - 1u) {
            // every block's g_loss add is fenced before its ticket increment
            out[0]   = __ldcg(&g_loss) * inv_batch;
            g_loss   = 0.0f;                               // restore invariants
            g_ticket = 0u;                                 // safe: all spins exited
        }
    }
}

// ---------------------------------------------------------------------------
// launch: ONE kernel node.
// ---------------------------------------------------------------------------
extern "C" void kernel_launch(void* const* d_in, const int* in_sizes, int n_in,
                              void* d_out, int out_size)
{
    const float* feat    = (const float*)d_in[0];
    const int*   label   = (const int*)d_in[1];
    const float* centers = (const float*)d_in[2];
    float*       out     = (float*)d_out;

    const int batch = in_sizes[1];                         // 16384

    centerloss_kernel<<<GRID_BLOCKS, BLOCK_THREADS>>>(
        feat, label, centers, out, batch, 1.0f / (float)batch);
}

// round 14
// speedup vs baseline: 1.1575x; 1.1150x over previous
#include <cuda_runtime.h>
#include <math.h>

#define NUM_CLASSES 10000
#define FEATURE_DIM 512

#define BLOCK_THREADS 1024       // 32 warps/CTA
#define GRID_BLOCKS   296        // 2 CTAs/SM * 148 SMs (<= 152*2 on GB300):
                                 // all CTAs co-resident -> spin-sync is safe
#define TOTAL_HALFWARPS (GRID_BLOCKS * (BLOCK_THREADS / 16))   // 18944 >= 16384

// Scratch (__device__ globals). Zero at load (.bss); the kernel restores all of
// them to zero each execution, so graph replays are deterministic.
__device__ float        g_dsum[NUM_CLASSES];
__device__ int          g_count[NUM_CLASSES];
__device__ float        g_loss;
__device__ unsigned int g_ticket;

// ---------------------------------------------------------------------------
// Single persistent kernel, one wave.
// Phase 1 (single pass): one HALF-WARP per sample. 512 floats = 128 float4;
//   16 lanes x 8 float4 per operand. Both half-warps of a warp run
//   concurrently -> 2x independent loads in flight vs warp/sample, and no
//   second dependent iteration.
// Grid sync: fence + ticket (296 arrivals) + spin.
// Phase 2: one class per thread across the grid; REDG into g_loss; second
//   ticket; last arrival writes the scalar and restores invariants.
// ---------------------------------------------------------------------------
__global__ void __launch_bounds__(BLOCK_THREADS, 2) centerloss_kernel(
    const float* __restrict__ feat,
    const int*   __restrict__ label,
    const float* __restrict__ centers,
    float*       __restrict__ out,
    int batch, float inv_batch)
{
    const int tid       = threadIdx.x;
    const int lane      = tid & 31;
    const int hlane     = tid & 15;                        // lane within half-warp
    const int hw_global = blockIdx.x * (BLOCK_THREADS / 16) + (tid >> 4);

    // ---------------- Phase 1: one sample per half-warp, single pass --------
    if (hw_global < batch) {
        const int s   = hw_global;
        const int lbl = label[s];                          // half-warp broadcast

        const float4* __restrict__ f =
            reinterpret_cast<const float4*>(feat + (size_t)s * FEATURE_DIM);
        const float4* __restrict__ c =
            reinterpret_cast<const float4*>(centers + (size_t)lbl * FEATURE_DIM);

        float acc = 0.0f;
        #pragma unroll
        for (int j = 0; j < FEATURE_DIM / 4 / 16; j++) {   // 8 iters -> 8 f4 + 8 f4
            float4 a = f[hlane + j * 16];                  // feat: streamed once
            float4 b = __ldg(&c[hlane + j * 16]);          // centers: L2 reuse
            float dx = a.x - b.x;
            float dy = a.y - b.y;
            float dz = a.z - b.z;
            float dw = a.w - b.w;
            acc = fmaf(dx, dx, acc);
            acc = fmaf(dy, dy, acc);
            acc = fmaf(dz, dz, acc);
            acc = fmaf(dw, dw, acc);
        }

        // reduce within the half-warp (xor offsets stay inside 16 lanes)
        #pragma unroll
        for (int o = 8; o > 0; o >>= 1)
            acc += __shfl_xor_sync(0xffffffffu, acc, o);

        if (hlane == 0) {                                  // lanes 0 and 16
            atomicAdd(&g_dsum[lbl], sqrtf(acc));           // spread-address REDG
            atomicAdd(&g_count[lbl], 1);
        }
    }

    // ---------------- Grid sync (296 arrivals, one wave) ----------------
    __syncthreads();
    if (tid == 0) {
        __threadfence();                                   // my atomics before arrive
        atomicAdd(&g_ticket, 1u);
        volatile unsigned int* tp = &g_ticket;
        while (*tp < (unsigned)gridDim.x) {                // all CTAs resident
            __nanosleep(64);
        }
    }
    __syncthreads();
    __threadfence();                                       // acquire side

    // ---------------- Phase 2: class reduction, whole grid ----------------
    float partial = 0.0f;
    const int cls = blockIdx.x * BLOCK_THREADS + tid;      // 303104 threads >= 10000
    if (cls < NUM_CLASSES) {
        int   cnt = __ldcg(&g_count[cls]);
        float ds  = __ldcg(&g_dsum[cls]);
        g_count[cls] = 0;                                  // restore invariant
        g_dsum[cls]  = 0.0f;
        if (cnt > 0) partial = ds / (float)cnt;
    }

    #pragma unroll
    for (int o = 16; o > 0; o >>= 1)
        partial += __shfl_xor_sync(0xffffffffu, partial, o);

    __shared__ float sred[BLOCK_THREADS / 32];
    if (lane == 0) sred[tid >> 5] = partial;
    __syncthreads();

    if (tid == 0) {
        float bsum = 0.0f;
        #pragma unroll
        for (int k = 0; k < BLOCK_THREADS / 32; k++) bsum += sred[k];
        atomicAdd(&g_loss, bsum);                          // 296 same-address REDG
        __threadfence();                                   // g_loss add before ticket
        unsigned t = atomicAdd(&g_ticket, 1u);             // grid .. 2*grid-1
        if (t == 2u * gridDim.x - 1u) {
            out[0]   = __ldcg(&g_loss) * inv_batch;
            g_loss   = 0.0f;                               // restore invariants
            g_ticket = 0u;                                 // all spins already exited
        }
    }
}

// ---------------------------------------------------------------------------
// launch: ONE kernel node.
// ---------------------------------------------------------------------------
extern "C" void kernel_launch(void* const* d_in, const int* in_sizes, int n_in,
                              void* d_out, int out_size)
{
    const float* feat    = (const float*)d_in[0];
    const int*   label   = (const int*)d_in[1];
    const float* centers = (const float*)d_in[2];
    float*       out     = (float*)d_out;

    const int batch = in_sizes[1];                         // 16384

    centerloss_kernel<<<GRID_BLOCKS, BLOCK_THREADS>>>(
        feat, label, centers, out, batch, 1.0f / (float)batch);
}